// round 14
// baseline (speedup 1.0000x reference)
#include <cuda_runtime.h>
#include <cuda_fp16.h>
#include <math.h>
#include <stdint.h>

// ============================================================================
// RegionAugmentedSelfAttention  (B=128, S=144, D=1024, GRID=12)
//   R14: R13's lean setup + isolated bias + proj, with the attention tail
//        reverted to the R10 split (scores_reg -> fp16 attn, av_h2).
//        (R13's flash fusion lost 47us in its PV phase: 3-warp CTAs
//         re-loading all of v with scalar transposes.)
// ============================================================================

#define B_  128
#define S_  144
#define D_  1024
#define BS_ (B_ * S_)          // 18432

// -------- scratch (static device globals) -----------------------------------
__device__ __align__(16) unsigned short g_ah[3 * BS_ * D_];  // half q/k/v inputs
__device__ __align__(16) unsigned short g_q[BS_ * D_];
__device__ __align__(16) unsigned short g_k[BS_ * D_];
__device__ __align__(16) unsigned short g_v[BS_ * D_];
__device__ __align__(16) unsigned short g_wt[3 * D_ * D_];   // half W^T (n,k)
__device__ __align__(16) unsigned short g_attn_h[B_ * S_ * S_]; // half attn
__device__ float g_bias[S_ * S_];

// ---------------------------------------------------------------------------
// helpers
// ---------------------------------------------------------------------------
__device__ __forceinline__ uint32_t pack_h2(float lo, float hi) {
    uint32_t r;
    asm("cvt.rn.f16x2.f32 %0, %1, %2;" : "=r"(r) : "f"(hi), "f"(lo));
    return r;
}

__device__ __forceinline__ void mma_h(float (&d)[4],
                                      const uint32_t (&a)[4],
                                      const uint32_t (&b)[2]) {
    asm volatile(
        "mma.sync.aligned.m16n8k16.row.col.f32.f16.f16.f32 "
        "{%0,%1,%2,%3}, {%4,%5,%6,%7}, {%8,%9}, {%0,%1,%2,%3};\n"
        : "+f"(d[0]), "+f"(d[1]), "+f"(d[2]), "+f"(d[3])
        : "r"(a[0]), "r"(a[1]), "r"(a[2]), "r"(a[3]),
          "r"(b[0]), "r"(b[1]));
}

__device__ __forceinline__ void ldsm_x4(uint32_t (&r)[4], uint32_t addr) {
    asm volatile("ldmatrix.sync.aligned.m8n8.x4.shared.b16 {%0,%1,%2,%3}, [%4];"
                 : "=r"(r[0]), "=r"(r[1]), "=r"(r[2]), "=r"(r[3]) : "r"(addr));
}

__device__ __forceinline__ void cp_async16(uint32_t smem_addr, const void* gptr) {
    asm volatile("cp.async.cg.shared.global [%0], [%1], 16;\n"
                 :: "r"(smem_addr), "l"(gptr));
}
#define CP_COMMIT()  asm volatile("cp.async.commit_group;\n")
#define CP_WAIT(N)   asm volatile("cp.async.wait_group %0;\n" :: "n"(N))

__device__ __forceinline__ uint32_t smem_u32p(const void* p) {
    return (uint32_t)__cvta_generic_to_shared(p);
}

// ============================================================================
// setup_fused: [0,27648) a2h | [27648,30720) transpose_w   (LEAN)
// ============================================================================
#define SETUP_A2H   27648
#define SETUP_TRANS 3072
#define SETUP_BLOCKS (SETUP_A2H + SETUP_TRANS)

__global__ __launch_bounds__(256)
void setup_fused(const float* __restrict__ q, const float* __restrict__ k,
                 const float* __restrict__ v, __half* __restrict__ ah,
                 const float* __restrict__ Wq, const float* __restrict__ Wk,
                 const float* __restrict__ Wv, __half* __restrict__ Wt)
{
    __shared__ float t[32][33];
    const int bid = blockIdx.x;
    const int tid = threadIdx.x;

    if (bid < SETUP_A2H) {
        const size_t per = (size_t)BS_ * D_ / 8;
        size_t i = (size_t)bid * 256 + tid;
        const float* src;
        size_t off;
        if (i < per)           { src = q; off = i; }
        else if (i < 2 * per)  { src = k; off = i - per; }
        else                   { src = v; off = i - 2 * per; }
        float4 x0 = ((const float4*)src)[off * 2];
        float4 x1 = ((const float4*)src)[off * 2 + 1];
        uint4 u = { pack_h2(x0.x, x0.y), pack_h2(x0.z, x0.w),
                    pack_h2(x1.x, x1.y), pack_h2(x1.z, x1.w) };
        ((uint4*)ah)[i] = u;
    } else {
        int b2 = bid - SETUP_A2H;
        int z = b2 >> 10;
        int rem = b2 & 1023;
        int bx = rem & 31, by = rem >> 5;
        const float* W = (z == 0) ? Wq : (z == 1) ? Wk : Wv;
        __half* O = Wt + (size_t)z * D_ * D_;
        int x0 = bx * 32, y0 = by * 32;
        int tx = tid & 31, ty = tid >> 5;
        #pragma unroll
        for (int r = ty; r < 32; r += 8)
            t[r][tx] = W[(size_t)(y0 + r) * D_ + x0 + tx];
        __syncthreads();
        #pragma unroll
        for (int r = ty; r < 32; r += 8)
            O[(size_t)(x0 + r) * D_ + y0 + tx] = __float2half(t[tx][r]);
    }
}

// ============================================================================
// bias_kernel: block (i, qt); rel computed inline. grid (144, 4).
// ============================================================================
__global__ __launch_bounds__(256)
void bias_kernel(const float* __restrict__ Wl, const float* __restrict__ bl,
                 const float* __restrict__ wg, float* __restrict__ bias)
{
    __shared__ float w[D_];
    __shared__ float Tp[36];
    const int i = blockIdx.x;
    const int qt = blockIdx.y;
    const int tid = threadIdx.x;

    *(float4*)&w[tid * 4] = *(const float4*)&wg[(size_t)i * D_ + tid * 4];
    __syncthreads();

    const int warp = tid >> 5;
    const int lane = tid & 31;
    for (int cl = warp; cl < 36; cl += 8) {
        int c = qt * 36 + cl;
        int a = c / 12, bb = c % 12;
        float dx = logf(fmaxf((float)a * 0.5f, 1e-10f));
        float dy = logf(fmaxf((float)bb * 0.5f, 1e-10f));
        float s = 0.f;
        #pragma unroll
        for (int d = lane * 4; d < D_; d += 128) {
            float4 l0 = *(const float4*)&Wl[d];
            float4 l1 = *(const float4*)&Wl[D_ + d];
            float4 b4 = *(const float4*)&bl[d];
            s += w[d]     * fmaxf(fmaf(dx, l0.x, fmaf(dy, l1.x, b4.x)), 0.f);
            s += w[d + 1] * fmaxf(fmaf(dx, l0.y, fmaf(dy, l1.y, b4.y)), 0.f);
            s += w[d + 2] * fmaxf(fmaf(dx, l0.z, fmaf(dy, l1.z, b4.z)), 0.f);
            s += w[d + 3] * fmaxf(fmaf(dx, l0.w, fmaf(dy, l1.w, b4.w)), 0.f);
        }
        #pragma unroll
        for (int o = 16; o; o >>= 1) s += __shfl_xor_sync(0xffffffffu, s, o);
        if (lane == 0) Tp[cl] = s;
    }
    __syncthreads();

    const int base = qt * 36;
    for (int j = tid; j < S_; j += 256) {
        int dr = abs(i / 12 - j / 12);
        int dc = abs(i % 12 - j % 12);
        int combo = dr * 12 + dc;
        if (combo >= base && combo < base + 36)
            bias[i * S_ + j] = fmaxf(Tp[combo - base], 0.f);
    }
}

// ============================================================================
// Projection GEMM  C = relu(A @ W + b)  -- fp16 HMMA (unchanged)
// ============================================================================
#define P3_STAGE 20480
#define PROJ_SMEM (3 * P3_STAGE)        // 61440 B

__global__ __launch_bounds__(256, 2)
void proj_h2(const __half* __restrict__ Ah, const __half* __restrict__ Wt,
             const float* __restrict__ bq, const float* __restrict__ bk,
             const float* __restrict__ bv,
             __half* __restrict__ Cq, __half* __restrict__ Ck,
             __half* __restrict__ Cv)
{
    extern __shared__ char smc[];
    const uint32_t sb = smem_u32p(smc);

    const int z = blockIdx.z;
    const __half* A  = Ah + (size_t)z * BS_ * D_;
    const __half* Bt = Wt + (size_t)z * D_ * D_;
    const float* bvec = (z == 0) ? bq : (z == 1) ? bk : bv;
    __half* C = (z == 0) ? Cq : (z == 1) ? Ck : Cv;

    const int tid  = threadIdx.x;
    const int lane = tid & 31;
    const int warp = tid >> 5;
    const int rowBase = blockIdx.y * 128;
    const int colBase = blockIdx.x * 128;
    const int warpRow = (warp >> 2) * 64;
    const int warpCol = (warp & 3) * 32;

    const int lr = tid >> 2;
    const int lc = tid & 3;
    const __half* Aga = A  + (size_t)(rowBase + lr) * D_ + lc * 8;
    const __half* Agb = A  + (size_t)(rowBase + lr + 64) * D_ + lc * 8;
    const __half* Bga = Bt + (size_t)(colBase + lr) * D_ + lc * 8;
    const __half* Bgb = Bt + (size_t)(colBase + lr + 64) * D_ + lc * 8;
    const uint32_t sAa = sb + lr * 80 + lc * 16;
    const uint32_t sAb = sAa + 64 * 80;
    const uint32_t sBa = sb + 10240 + lr * 80 + lc * 16;
    const uint32_t sBb = sBa + 64 * 80;

    const uint32_t aBase = sb + (uint32_t)((warpRow + (lane & 15)) * 80 + (lane >> 4) * 16);
    const uint32_t bBase = sb + 10240 +
        (uint32_t)((warpCol + (lane & 7) + ((lane >> 4) & 1) * 8) * 80 +
                   ((lane >> 3) & 1) * 16);

    float acc[4][4][4];
    #pragma unroll
    for (int i = 0; i < 4; i++)
        #pragma unroll
        for (int j = 0; j < 4; j++)
            #pragma unroll
            for (int r = 0; r < 4; r++) acc[i][j][r] = 0.f;

    const int NKT = D_ / 32;

    #pragma unroll
    for (int s = 0; s < 2; s++) {
        uint32_t so = s * P3_STAGE;
        cp_async16(sAa + so, Aga + s * 32);
        cp_async16(sAb + so, Agb + s * 32);
        cp_async16(sBa + so, Bga + s * 32);
        cp_async16(sBb + so, Bgb + s * 32);
        CP_COMMIT();
    }

    int stage = 0;
    for (int kt = 0; kt < NKT; kt++) {
        if (kt >= NKT - 2) { CP_WAIT(0); } else { CP_WAIT(1); }
        __syncthreads();

        if (kt + 2 < NKT) {
            int ns = (kt + 2) % 3;
            uint32_t so = ns * P3_STAGE;
            int ko = (kt + 2) * 32;
            cp_async16(sAa + so, Aga + ko);
            cp_async16(sAb + so, Agb + ko);
            cp_async16(sBa + so, Bga + ko);
            cp_async16(sBb + so, Bgb + ko);
            CP_COMMIT();
        }

        const uint32_t so = stage * P3_STAGE;
        #pragma unroll
        for (int ks = 0; ks < 2; ks++) {
            uint32_t af[4][4], bp[2][4];
            #pragma unroll
            for (int mt = 0; mt < 4; mt++)
                ldsm_x4(af[mt], aBase + so + mt * (16 * 80) + ks * 32);
            #pragma unroll
            for (int p = 0; p < 2; p++)
                ldsm_x4(bp[p], bBase + so + p * (16 * 80) + ks * 32);
            #pragma unroll
            for (int mt = 0; mt < 4; mt++) {
                #pragma unroll
                for (int p = 0; p < 2; p++) {
                    uint32_t b0[2] = { bp[p][0], bp[p][1] };
                    uint32_t b1[2] = { bp[p][2], bp[p][3] };
                    mma_h(acc[mt][p * 2],     af[mt], b0);
                    mma_h(acc[mt][p * 2 + 1], af[mt], b1);
                }
            }
        }
        stage = (stage + 1) % 3;
        __syncthreads();
    }

    const int g = lane >> 2;
    const int t = lane & 3;
    #pragma unroll
    for (int mt = 0; mt < 4; mt++) {
        int r = rowBase + warpRow + mt * 16 + g;
        #pragma unroll
        for (int nt = 0; nt < 4; nt++) {
            int c = colBase + warpCol + nt * 8 + 2 * t;
            float b0 = bvec[c], b1 = bvec[c + 1];
            uint32_t h0 = pack_h2(fmaxf(acc[mt][nt][0] + b0, 0.f),
                                  fmaxf(acc[mt][nt][1] + b1, 0.f));
            uint32_t h1 = pack_h2(fmaxf(acc[mt][nt][2] + b0, 0.f),
                                  fmaxf(acc[mt][nt][3] + b1, 0.f));
            *(uint32_t*)&C[(size_t)r * D_ + c]       = h0;
            *(uint32_t*)&C[(size_t)(r + 8) * D_ + c] = h1;
        }
    }
}

// ============================================================================
// scores_reg (R10): QK^T + bias -> softmax -> fp16 attn. grid (3, 128), 96 thr.
// ============================================================================
#define S3_STAGE 15360
#define S3_PART  (2 * S3_STAGE)
#define SCORES_SMEM3 (S3_PART + 48 * 4 * 4 * 2)   // 32256 B

__global__ __launch_bounds__(96)
void scores_reg(const __half* __restrict__ q, const __half* __restrict__ k,
                const float* __restrict__ bias, __half* __restrict__ attn_h,
                float scale)
{
    extern __shared__ char smc[];
    const uint32_t sb = smem_u32p(smc);
    float* pmax = (float*)(smc + S3_PART);
    float* psum = pmax + 48 * 4;

    const int b = blockIdx.y;
    const int rowBase = blockIdx.x * 48;
    const __half* qb = q + (size_t)b * S_ * D_;
    const __half* kb = k + (size_t)b * S_ * D_;

    const int tid  = threadIdx.x;
    const int lane = tid & 31;
    const int warp = tid >> 5;
    const int g = lane >> 2;
    const int t = lane & 3;
    const int warpCol = warp * 48;

    const int lr = tid >> 2;
    const int lc = tid & 3;
    const __half* qg = qb + (size_t)(rowBase + lr) * D_ + lc * 8;
    const __half* kg = kb + (size_t)lr * D_ + lc * 8;
    const uint32_t sL = sb + lr * 80 + lc * 16;

    const uint32_t aBase = sb + (uint32_t)((lane & 15) * 80 + (lane >> 4) * 16);
    const uint32_t bBase = sb + 48 * 80 +
        (uint32_t)((warpCol + (lane & 7) + ((lane >> 4) & 1) * 8) * 80 +
                   ((lane >> 3) & 1) * 16);

    float acc[3][6][4];
    #pragma unroll
    for (int i = 0; i < 3; i++)
        #pragma unroll
        for (int j = 0; j < 6; j++)
            #pragma unroll
            for (int r = 0; r < 4; r++) acc[i][j][r] = 0.f;

    const int NKT = D_ / 32;

    #pragma unroll
    for (int j = 0; j < 2; j++)
        cp_async16(sL + j * (24 * 80), qg + (size_t)j * 24 * D_);
    #pragma unroll
    for (int j = 0; j < 6; j++)
        cp_async16(sL + (j + 2) * (24 * 80), kg + (size_t)j * 24 * D_);
    CP_COMMIT();

    for (int kt = 0; kt < NKT; kt++) {
        const int cur = kt & 1;
        if (kt + 1 < NKT) {
            const int nxt = cur ^ 1;
            const int ko = (kt + 1) * 32;
            #pragma unroll
            for (int j = 0; j < 2; j++)
                cp_async16(sL + nxt * S3_STAGE + j * (24 * 80),
                           qg + (size_t)j * 24 * D_ + ko);
            #pragma unroll
            for (int j = 0; j < 6; j++)
                cp_async16(sL + nxt * S3_STAGE + (j + 2) * (24 * 80),
                           kg + (size_t)j * 24 * D_ + ko);
            CP_COMMIT();
            CP_WAIT(1);
        } else {
            CP_WAIT(0);
        }
        __syncthreads();

        const uint32_t so = cur * S3_STAGE;
        #pragma unroll
        for (int ks = 0; ks < 2; ks++) {
            uint32_t af[3][4], bp[3][4];
            #pragma unroll
            for (int mt = 0; mt < 3; mt++)
                ldsm_x4(af[mt], aBase + so + mt * (16 * 80) + ks * 32);
            #pragma unroll
            for (int p = 0; p < 3; p++)
                ldsm_x4(bp[p], bBase + so + p * (16 * 80) + ks * 32);
            #pragma unroll
            for (int mt = 0; mt < 3; mt++) {
                #pragma unroll
                for (int p = 0; p < 3; p++) {
                    uint32_t b0[2] = { bp[p][0], bp[p][1] };
                    uint32_t b1[2] = { bp[p][2], bp[p][3] };
                    mma_h(acc[mt][p * 2],     af[mt], b0);
                    mma_h(acc[mt][p * 2 + 1], af[mt], b1);
                }
            }
        }
        __syncthreads();
    }

    #pragma unroll
    for (int mt = 0; mt < 3; mt++) {
        int m = rowBase + mt * 16 + g;
        #pragma unroll
        for (int nt = 0; nt < 6; nt++) {
            int n = warpCol + nt * 8 + 2 * t;
            float2 bA = *(const float2*)&bias[m * S_ + n];
            float2 bB = *(const float2*)&bias[(m + 8) * S_ + n];
            acc[mt][nt][0] = fmaf(acc[mt][nt][0], scale, bA.x);
            acc[mt][nt][1] = fmaf(acc[mt][nt][1], scale, bA.y);
            acc[mt][nt][2] = fmaf(acc[mt][nt][2], scale, bB.x);
            acc[mt][nt][3] = fmaf(acc[mt][nt][3], scale, bB.y);
        }
    }

    float mx0[3], mx1[3];
    #pragma unroll
    for (int mt = 0; mt < 3; mt++) {
        float a0 = -INFINITY, a1 = -INFINITY;
        #pragma unroll
        for (int nt = 0; nt < 6; nt++) {
            a0 = fmaxf(a0, fmaxf(acc[mt][nt][0], acc[mt][nt][1]));
            a1 = fmaxf(a1, fmaxf(acc[mt][nt][2], acc[mt][nt][3]));
        }
        #pragma unroll
        for (int o = 1; o < 4; o <<= 1) {
            a0 = fmaxf(a0, __shfl_xor_sync(0xffffffffu, a0, o));
            a1 = fmaxf(a1, __shfl_xor_sync(0xffffffffu, a1, o));
        }
        mx0[mt] = a0; mx1[mt] = a1;
        if (t == 0) {
            pmax[(mt * 16 + g) * 4 + warp]     = a0;
            pmax[(mt * 16 + g + 8) * 4 + warp] = a1;
        }
    }
    __syncthreads();
    #pragma unroll
    for (int mt = 0; mt < 3; mt++) {
        int r0 = (mt * 16 + g) * 4, r1 = (mt * 16 + g + 8) * 4;
        mx0[mt] = fmaxf(fmaxf(pmax[r0], pmax[r0 + 1]), pmax[r0 + 2]);
        mx1[mt] = fmaxf(fmaxf(pmax[r1], pmax[r1 + 1]), pmax[r1 + 2]);
    }

    #pragma unroll
    for (int mt = 0; mt < 3; mt++) {
        float a0 = 0.f, a1 = 0.f;
        #pragma unroll
        for (int nt = 0; nt < 6; nt++) {
            acc[mt][nt][0] = __expf(acc[mt][nt][0] - mx0[mt]);
            acc[mt][nt][1] = __expf(acc[mt][nt][1] - mx0[mt]);
            acc[mt][nt][2] = __expf(acc[mt][nt][2] - mx1[mt]);
            acc[mt][nt][3] = __expf(acc[mt][nt][3] - mx1[mt]);
            a0 += acc[mt][nt][0] + acc[mt][nt][1];
            a1 += acc[mt][nt][2] + acc[mt][nt][3];
        }
        #pragma unroll
        for (int o = 1; o < 4; o <<= 1) {
            a0 += __shfl_xor_sync(0xffffffffu, a0, o);
            a1 += __shfl_xor_sync(0xffffffffu, a1, o);
        }
        if (t == 0) {
            psum[(mt * 16 + g) * 4 + warp]     = a0;
            psum[(mt * 16 + g + 8) * 4 + warp] = a1;
        }
    }
    __syncthreads();

    __half* ao = attn_h + (size_t)b * S_ * S_;
    #pragma unroll
    for (int mt = 0; mt < 3; mt++) {
        int r0 = (mt * 16 + g) * 4, r1 = (mt * 16 + g + 8) * 4;
        float i0 = 1.f / (psum[r0] + psum[r0 + 1] + psum[r0 + 2]);
        float i1 = 1.f / (psum[r1] + psum[r1 + 1] + psum[r1 + 2]);
        int m = rowBase + mt * 16 + g;
        #pragma unroll
        for (int nt = 0; nt < 6; nt++) {
            int n = warpCol + nt * 8 + 2 * t;
            *(uint32_t*)&ao[(size_t)m * S_ + n] =
                pack_h2(acc[mt][nt][0] * i0, acc[mt][nt][1] * i0);
            *(uint32_t*)&ao[(size_t)(m + 8) * S_ + n] =
                pack_h2(acc[mt][nt][2] * i1, acc[mt][nt][3] * i1);
        }
    }
}

// ============================================================================
// av_h2 (R10): out = attn_h @ v.  grid (8, 128), 384 thr.
// ============================================================================
#define AV_SMEM ((144 * 28 + 128 * 28) * 4)

__global__ __launch_bounds__(384, 1)
void av_h2(const __half* __restrict__ attn_h, const __half* __restrict__ v,
           float* __restrict__ out)
{
    extern __shared__ uint32_t smu[];
    uint32_t* An = smu;
    uint32_t* Vs = smu + 144 * 28;

    const int b = blockIdx.y;
    const int colBase = blockIdx.x * 128;
    const __half* ab = attn_h + (size_t)b * S_ * S_;
    const __half* vb = v + (size_t)b * S_ * D_;

    const int tid  = threadIdx.x;
    const int lane = tid & 31;
    const int warp = tid >> 5;
    const int g = lane >> 2;
    const int t = lane & 3;
    const int warpRow = (warp >> 2) * 48;
    const int warpCol = (warp & 3) * 32;

    float acc[3][4][4];
    #pragma unroll
    for (int i = 0; i < 3; i++)
        #pragma unroll
        for (int j = 0; j < 4; j++)
            #pragma unroll
            for (int r = 0; r < 4; r++) acc[i][j][r] = 0.f;

    for (int k0 = 0; k0 < S_; k0 += 48) {
        for (int idx = tid; idx < 144 * 6; idx += 384) {
            int rr = idx / 6, cc = idx % 6;
            uint4 u = *(const uint4*)&ab[rr * S_ + k0 + cc * 8];
            *(uint4*)&An[rr * 28 + cc * 4] = u;
        }
        unsigned short* vs16 = (unsigned short*)Vs;
        #pragma unroll
        for (int j = 0; j < 2; j++) {
            int idx = tid + j * 384;
            int tk = idx >> 4;
            int dch = idx & 15;
            uint4 u = *(const uint4*)&vb[(size_t)(k0 + tk) * D_ + colBase + dch * 8];
            const unsigned short* hs = (const unsigned short*)&u;
            #pragma unroll
            for (int e = 0; e < 8; e++)
                vs16[(dch * 8 + e) * 56 + tk] = hs[e];
        }
        __syncthreads();

        #pragma unroll
        for (int ks = 0; ks < 3; ks++) {
            const int kd = ks * 8;
            uint32_t af[3][4], bf[4][2];
            #pragma unroll
            for (int mt = 0; mt < 3; mt++) {
                int m0 = warpRow + mt * 16;
                af[mt][0] = An[(m0 + g)     * 28 + kd + t];
                af[mt][1] = An[(m0 + g + 8) * 28 + kd + t];
                af[mt][2] = An[(m0 + g)     * 28 + kd + t + 4];
                af[mt][3] = An[(m0 + g + 8) * 28 + kd + t + 4];
            }
            #pragma unroll
            for (int nt = 0; nt < 4; nt++) {
                int n0 = warpCol + nt * 8;
                bf[nt][0] = Vs[(n0 + g) * 28 + kd + t];
                bf[nt][1] = Vs[(n0 + g) * 28 + kd + t + 4];
            }
            #pragma unroll
            for (int mt = 0; mt < 3; mt++)
                #pragma unroll
                for (int nt = 0; nt < 4; nt++)
                    mma_h(acc[mt][nt], af[mt], bf[nt]);
        }
        __syncthreads();
    }

    #pragma unroll
    for (int mt = 0; mt < 3; mt++) {
        int m = warpRow + mt * 16 + g;
        #pragma unroll
        for (int nt = 0; nt < 4; nt++) {
            int n = colBase + warpCol + nt * 8 + 2 * t;
            float2 o0 = { acc[mt][nt][0], acc[mt][nt][1] };
            float2 o1 = { acc[mt][nt][2], acc[mt][nt][3] };
            *(float2*)&out[((size_t)b * S_ + m) * D_ + n]     = o0;
            *(float2*)&out[((size_t)b * S_ + m + 8) * D_ + n] = o1;
        }
    }
}

// ============================================================================
// launch — 5 kernels, single stream
// ============================================================================
extern "C" void kernel_launch(void* const* d_in, const int* in_sizes, int n_in,
                              void* d_out, int out_size)
{
    const float* query = (const float*)d_in[0];
    const float* key   = (const float*)d_in[1];
    const float* value = (const float*)d_in[2];
    const float* Wq    = (const float*)d_in[3];
    const float* bq    = (const float*)d_in[4];
    const float* Wk    = (const float*)d_in[5];
    const float* bk    = (const float*)d_in[6];
    const float* Wv    = (const float*)d_in[7];
    const float* bv    = (const float*)d_in[8];
    const float* Wl    = (const float*)d_in[9];
    const float* bl    = (const float*)d_in[10];
    const float* wg    = (const float*)d_in[11];
    float* out = (float*)d_out;

    __half* ah;   cudaGetSymbolAddress((void**)&ah,   g_ah);
    __half* qh;   cudaGetSymbolAddress((void**)&qh,   g_q);
    __half* kh;   cudaGetSymbolAddress((void**)&kh,   g_k);
    __half* vh;   cudaGetSymbolAddress((void**)&vh,   g_v);
    __half* wt;   cudaGetSymbolAddress((void**)&wt,   g_wt);
    __half* athh; cudaGetSymbolAddress((void**)&athh, g_attn_h);
    float* bias;  cudaGetSymbolAddress((void**)&bias, g_bias);

    cudaFuncSetAttribute(proj_h2,
                         cudaFuncAttributeMaxDynamicSharedMemorySize, PROJ_SMEM);
    cudaFuncSetAttribute(scores_reg,
                         cudaFuncAttributeMaxDynamicSharedMemorySize, SCORES_SMEM3);
    cudaFuncSetAttribute(av_h2,
                         cudaFuncAttributeMaxDynamicSharedMemorySize, AV_SMEM);

    float scale = 1.0f / sqrtf((float)D_);

    // 1. setup: input cvt + weight transpose (lean)
    setup_fused<<<SETUP_BLOCKS, 256>>>(query, key, value, ah, Wq, Wk, Wv, wt);

    // 2. bias table (rel inline, register-heavy, isolated)
    bias_kernel<<<dim3(144, 4), 256>>>(Wl, bl, wg, bias);

    // 3. projections (fp16 HMMA)
    proj_h2<<<dim3(8, 144, 3), 256, PROJ_SMEM>>>(ah, wt, bq, bk, bv, qh, kh, vh);

    // 4. scores + softmax -> fp16 attn
    scores_reg<<<dim3(3, B_), 96, SCORES_SMEM3>>>(qh, kh, bias, athh, scale);

    // 5. out = attn @ v
    av_h2<<<dim3(D_ / 128, B_), 384, AV_SMEM>>>(athh, vh, out);
}

// round 15
// speedup vs baseline: 1.0956x; 1.0956x over previous
#include <cuda_runtime.h>
#include <cuda_fp16.h>
#include <math.h>
#include <stdint.h>

// ============================================================================
// RegionAugmentedSelfAttention  (B=128, S=144, D=1024, GRID=12)
//   R15: R13 (flash-fused scores_av, best arch) with the PV phase rebuilt:
//        v chunk stored row-major via uint4 (no scalar transpose) and
//        B fragments loaded with ldmatrix.x4.trans.
// ============================================================================

#define B_  128
#define S_  144
#define D_  1024
#define BS_ (B_ * S_)          // 18432

// -------- scratch (static device globals) -----------------------------------
__device__ __align__(16) unsigned short g_ah[3 * BS_ * D_];  // half q/k/v inputs
__device__ __align__(16) unsigned short g_q[BS_ * D_];
__device__ __align__(16) unsigned short g_k[BS_ * D_];
__device__ __align__(16) unsigned short g_v[BS_ * D_];
__device__ __align__(16) unsigned short g_wt[3 * D_ * D_];   // half W^T (n,k)
__device__ float g_bias[S_ * S_];

// ---------------------------------------------------------------------------
// helpers
// ---------------------------------------------------------------------------
__device__ __forceinline__ uint32_t pack_h2(float lo, float hi) {
    uint32_t r;
    asm("cvt.rn.f16x2.f32 %0, %1, %2;" : "=r"(r) : "f"(hi), "f"(lo));
    return r;
}

__device__ __forceinline__ void mma_h(float (&d)[4],
                                      const uint32_t (&a)[4],
                                      const uint32_t (&b)[2]) {
    asm volatile(
        "mma.sync.aligned.m16n8k16.row.col.f32.f16.f16.f32 "
        "{%0,%1,%2,%3}, {%4,%5,%6,%7}, {%8,%9}, {%0,%1,%2,%3};\n"
        : "+f"(d[0]), "+f"(d[1]), "+f"(d[2]), "+f"(d[3])
        : "r"(a[0]), "r"(a[1]), "r"(a[2]), "r"(a[3]),
          "r"(b[0]), "r"(b[1]));
}

__device__ __forceinline__ void ldsm_x4(uint32_t (&r)[4], uint32_t addr) {
    asm volatile("ldmatrix.sync.aligned.m8n8.x4.shared.b16 {%0,%1,%2,%3}, [%4];"
                 : "=r"(r[0]), "=r"(r[1]), "=r"(r[2]), "=r"(r[3]) : "r"(addr));
}

__device__ __forceinline__ void ldsm_x4_t(uint32_t (&r)[4], uint32_t addr) {
    asm volatile("ldmatrix.sync.aligned.m8n8.x4.trans.shared.b16 {%0,%1,%2,%3}, [%4];"
                 : "=r"(r[0]), "=r"(r[1]), "=r"(r[2]), "=r"(r[3]) : "r"(addr));
}

__device__ __forceinline__ void cp_async16(uint32_t smem_addr, const void* gptr) {
    asm volatile("cp.async.cg.shared.global [%0], [%1], 16;\n"
                 :: "r"(smem_addr), "l"(gptr));
}
#define CP_COMMIT()  asm volatile("cp.async.commit_group;\n")
#define CP_WAIT(N)   asm volatile("cp.async.wait_group %0;\n" :: "n"(N))

__device__ __forceinline__ uint32_t smem_u32p(const void* p) {
    return (uint32_t)__cvta_generic_to_shared(p);
}

// ============================================================================
// setup_fused: [0,27648) a2h | [27648,30720) transpose_w   (LEAN)
// ============================================================================
#define SETUP_A2H   27648
#define SETUP_TRANS 3072
#define SETUP_BLOCKS (SETUP_A2H + SETUP_TRANS)

__global__ __launch_bounds__(256)
void setup_fused(const float* __restrict__ q, const float* __restrict__ k,
                 const float* __restrict__ v, __half* __restrict__ ah,
                 const float* __restrict__ Wq, const float* __restrict__ Wk,
                 const float* __restrict__ Wv, __half* __restrict__ Wt)
{
    __shared__ float t[32][33];
    const int bid = blockIdx.x;
    const int tid = threadIdx.x;

    if (bid < SETUP_A2H) {
        const size_t per = (size_t)BS_ * D_ / 8;
        size_t i = (size_t)bid * 256 + tid;
        const float* src;
        size_t off;
        if (i < per)           { src = q; off = i; }
        else if (i < 2 * per)  { src = k; off = i - per; }
        else                   { src = v; off = i - 2 * per; }
        float4 x0 = ((const float4*)src)[off * 2];
        float4 x1 = ((const float4*)src)[off * 2 + 1];
        uint4 u = { pack_h2(x0.x, x0.y), pack_h2(x0.z, x0.w),
                    pack_h2(x1.x, x1.y), pack_h2(x1.z, x1.w) };
        ((uint4*)ah)[i] = u;
    } else {
        int b2 = bid - SETUP_A2H;
        int z = b2 >> 10;
        int rem = b2 & 1023;
        int bx = rem & 31, by = rem >> 5;
        const float* W = (z == 0) ? Wq : (z == 1) ? Wk : Wv;
        __half* O = Wt + (size_t)z * D_ * D_;
        int x0 = bx * 32, y0 = by * 32;
        int tx = tid & 31, ty = tid >> 5;
        #pragma unroll
        for (int r = ty; r < 32; r += 8)
            t[r][tx] = W[(size_t)(y0 + r) * D_ + x0 + tx];
        __syncthreads();
        #pragma unroll
        for (int r = ty; r < 32; r += 8)
            O[(size_t)(x0 + r) * D_ + y0 + tx] = __float2half(t[tx][r]);
    }
}

// ============================================================================
// bias_kernel: block (i, qt); rel computed inline. grid (144, 4).
// ============================================================================
__global__ __launch_bounds__(256)
void bias_kernel(const float* __restrict__ Wl, const float* __restrict__ bl,
                 const float* __restrict__ wg, float* __restrict__ bias)
{
    __shared__ float w[D_];
    __shared__ float Tp[36];
    const int i = blockIdx.x;
    const int qt = blockIdx.y;
    const int tid = threadIdx.x;

    *(float4*)&w[tid * 4] = *(const float4*)&wg[(size_t)i * D_ + tid * 4];
    __syncthreads();

    const int warp = tid >> 5;
    const int lane = tid & 31;
    for (int cl = warp; cl < 36; cl += 8) {
        int c = qt * 36 + cl;
        int a = c / 12, bb = c % 12;
        float dx = logf(fmaxf((float)a * 0.5f, 1e-10f));
        float dy = logf(fmaxf((float)bb * 0.5f, 1e-10f));
        float s = 0.f;
        #pragma unroll
        for (int d = lane * 4; d < D_; d += 128) {
            float4 l0 = *(const float4*)&Wl[d];
            float4 l1 = *(const float4*)&Wl[D_ + d];
            float4 b4 = *(const float4*)&bl[d];
            s += w[d]     * fmaxf(fmaf(dx, l0.x, fmaf(dy, l1.x, b4.x)), 0.f);
            s += w[d + 1] * fmaxf(fmaf(dx, l0.y, fmaf(dy, l1.y, b4.y)), 0.f);
            s += w[d + 2] * fmaxf(fmaf(dx, l0.z, fmaf(dy, l1.z, b4.z)), 0.f);
            s += w[d + 3] * fmaxf(fmaf(dx, l0.w, fmaf(dy, l1.w, b4.w)), 0.f);
        }
        #pragma unroll
        for (int o = 16; o; o >>= 1) s += __shfl_xor_sync(0xffffffffu, s, o);
        if (lane == 0) Tp[cl] = s;
    }
    __syncthreads();

    const int base = qt * 36;
    for (int j = tid; j < S_; j += 256) {
        int dr = abs(i / 12 - j / 12);
        int dc = abs(i % 12 - j % 12);
        int combo = dr * 12 + dc;
        if (combo >= base && combo < base + 36)
            bias[i * S_ + j] = fmaxf(Tp[combo - base], 0.f);
    }
}

// ============================================================================
// Projection GEMM  C = relu(A @ W + b)  -- fp16 HMMA (unchanged)
// ============================================================================
#define P3_STAGE 20480
#define PROJ_SMEM (3 * P3_STAGE)        // 61440 B

__global__ __launch_bounds__(256, 2)
void proj_h2(const __half* __restrict__ Ah, const __half* __restrict__ Wt,
             const float* __restrict__ bq, const float* __restrict__ bk,
             const float* __restrict__ bv,
             __half* __restrict__ Cq, __half* __restrict__ Ck,
             __half* __restrict__ Cv)
{
    extern __shared__ char smc[];
    const uint32_t sb = smem_u32p(smc);

    const int z = blockIdx.z;
    const __half* A  = Ah + (size_t)z * BS_ * D_;
    const __half* Bt = Wt + (size_t)z * D_ * D_;
    const float* bvec = (z == 0) ? bq : (z == 1) ? bk : bv;
    __half* C = (z == 0) ? Cq : (z == 1) ? Ck : Cv;

    const int tid  = threadIdx.x;
    const int lane = tid & 31;
    const int warp = tid >> 5;
    const int rowBase = blockIdx.y * 128;
    const int colBase = blockIdx.x * 128;
    const int warpRow = (warp >> 2) * 64;
    const int warpCol = (warp & 3) * 32;

    const int lr = tid >> 2;
    const int lc = tid & 3;
    const __half* Aga = A  + (size_t)(rowBase + lr) * D_ + lc * 8;
    const __half* Agb = A  + (size_t)(rowBase + lr + 64) * D_ + lc * 8;
    const __half* Bga = Bt + (size_t)(colBase + lr) * D_ + lc * 8;
    const __half* Bgb = Bt + (size_t)(colBase + lr + 64) * D_ + lc * 8;
    const uint32_t sAa = sb + lr * 80 + lc * 16;
    const uint32_t sAb = sAa + 64 * 80;
    const uint32_t sBa = sb + 10240 + lr * 80 + lc * 16;
    const uint32_t sBb = sBa + 64 * 80;

    const uint32_t aBase = sb + (uint32_t)((warpRow + (lane & 15)) * 80 + (lane >> 4) * 16);
    const uint32_t bBase = sb + 10240 +
        (uint32_t)((warpCol + (lane & 7) + ((lane >> 4) & 1) * 8) * 80 +
                   ((lane >> 3) & 1) * 16);

    float acc[4][4][4];
    #pragma unroll
    for (int i = 0; i < 4; i++)
        #pragma unroll
        for (int j = 0; j < 4; j++)
            #pragma unroll
            for (int r = 0; r < 4; r++) acc[i][j][r] = 0.f;

    const int NKT = D_ / 32;

    #pragma unroll
    for (int s = 0; s < 2; s++) {
        uint32_t so = s * P3_STAGE;
        cp_async16(sAa + so, Aga + s * 32);
        cp_async16(sAb + so, Agb + s * 32);
        cp_async16(sBa + so, Bga + s * 32);
        cp_async16(sBb + so, Bgb + s * 32);
        CP_COMMIT();
    }

    int stage = 0;
    for (int kt = 0; kt < NKT; kt++) {
        if (kt >= NKT - 2) { CP_WAIT(0); } else { CP_WAIT(1); }
        __syncthreads();

        if (kt + 2 < NKT) {
            int ns = (kt + 2) % 3;
            uint32_t so = ns * P3_STAGE;
            int ko = (kt + 2) * 32;
            cp_async16(sAa + so, Aga + ko);
            cp_async16(sAb + so, Agb + ko);
            cp_async16(sBa + so, Bga + ko);
            cp_async16(sBb + so, Bgb + ko);
            CP_COMMIT();
        }

        const uint32_t so = stage * P3_STAGE;
        #pragma unroll
        for (int ks = 0; ks < 2; ks++) {
            uint32_t af[4][4], bp[2][4];
            #pragma unroll
            for (int mt = 0; mt < 4; mt++)
                ldsm_x4(af[mt], aBase + so + mt * (16 * 80) + ks * 32);
            #pragma unroll
            for (int p = 0; p < 2; p++)
                ldsm_x4(bp[p], bBase + so + p * (16 * 80) + ks * 32);
            #pragma unroll
            for (int mt = 0; mt < 4; mt++) {
                #pragma unroll
                for (int p = 0; p < 2; p++) {
                    uint32_t b0[2] = { bp[p][0], bp[p][1] };
                    uint32_t b1[2] = { bp[p][2], bp[p][3] };
                    mma_h(acc[mt][p * 2],     af[mt], b0);
                    mma_h(acc[mt][p * 2 + 1], af[mt], b1);
                }
            }
        }
        stage = (stage + 1) % 3;
        __syncthreads();
    }

    const int g = lane >> 2;
    const int t = lane & 3;
    #pragma unroll
    for (int mt = 0; mt < 4; mt++) {
        int r = rowBase + warpRow + mt * 16 + g;
        #pragma unroll
        for (int nt = 0; nt < 4; nt++) {
            int c = colBase + warpCol + nt * 8 + 2 * t;
            float b0 = bvec[c], b1 = bvec[c + 1];
            uint32_t h0 = pack_h2(fmaxf(acc[mt][nt][0] + b0, 0.f),
                                  fmaxf(acc[mt][nt][1] + b1, 0.f));
            uint32_t h1 = pack_h2(fmaxf(acc[mt][nt][2] + b0, 0.f),
                                  fmaxf(acc[mt][nt][3] + b1, 0.f));
            *(uint32_t*)&C[(size_t)r * D_ + c]       = h0;
            *(uint32_t*)&C[(size_t)(r + 8) * D_ + c] = h1;
        }
    }
}

// ============================================================================
// scores_av: fused  out = softmax(qk^T*scale + bias) @ v
//   QK phase unchanged from R13. PV phase: v chunk row-major [144][72 halves]
//   (uint4 fill, no scalar transpose), B frags via ldmatrix.x4.trans.
//   smem: max(QK 30720 B, PV 144*144=20736 B) = 30720 B.
// ============================================================================
#define S3_STAGE 15360
#define SAV_SMEM (2 * S3_STAGE)    // 30720 B
#define VROW 144                   // PV v-chunk row stride in bytes (72 halves)

__global__ __launch_bounds__(96)
void scores_av(const __half* __restrict__ q, const __half* __restrict__ k,
               const __half* __restrict__ v, const float* __restrict__ bias,
               float* __restrict__ out, float scale)
{
    extern __shared__ char smc[];
    const uint32_t sb = smem_u32p(smc);

    const int b = blockIdx.y;
    const int rowBase = blockIdx.x * 48;
    const __half* qb = q + (size_t)b * S_ * D_;
    const __half* kb = k + (size_t)b * S_ * D_;
    const __half* vb = v + (size_t)b * S_ * D_;

    const int tid  = threadIdx.x;
    const int lane = tid & 31;
    const int warp = tid >> 5;
    const int g = lane >> 2;
    const int t = lane & 3;

    // ---- QK loaders ----
    const int lr = tid >> 2;
    const int lc = tid & 3;
    const __half* qg = qb + (size_t)(rowBase + lr) * D_ + lc * 8;
    const __half* kg = kb + (size_t)lr * D_ + lc * 8;
    const uint32_t sL = sb + lr * 80 + lc * 16;

    const uint32_t aBase = sb + (uint32_t)((warp * 16 + (lane & 15)) * 80 +
                                           (lane >> 4) * 16);
    const uint32_t bBase = sb + 48 * 80 +
        (uint32_t)(((lane & 7) + ((lane >> 4) & 1) * 8) * 80 +
                   ((lane >> 3) & 1) * 16);

    float acc[18][4];
    #pragma unroll
    for (int j = 0; j < 18; j++)
        #pragma unroll
        for (int r = 0; r < 4; r++) acc[j][r] = 0.f;

    const int NKT = D_ / 32;

    #pragma unroll
    for (int j = 0; j < 2; j++)
        cp_async16(sL + j * (24 * 80), qg + (size_t)j * 24 * D_);
    #pragma unroll
    for (int j = 0; j < 6; j++)
        cp_async16(sL + (j + 2) * (24 * 80), kg + (size_t)j * 24 * D_);
    CP_COMMIT();

    for (int kt = 0; kt < NKT; kt++) {
        const int cur = kt & 1;
        if (kt + 1 < NKT) {
            const int nxt = cur ^ 1;
            const int ko = (kt + 1) * 32;
            #pragma unroll
            for (int j = 0; j < 2; j++)
                cp_async16(sL + nxt * S3_STAGE + j * (24 * 80),
                           qg + (size_t)j * 24 * D_ + ko);
            #pragma unroll
            for (int j = 0; j < 6; j++)
                cp_async16(sL + nxt * S3_STAGE + (j + 2) * (24 * 80),
                           kg + (size_t)j * 24 * D_ + ko);
            CP_COMMIT();
            CP_WAIT(1);
        } else {
            CP_WAIT(0);
        }
        __syncthreads();

        const uint32_t so = cur * S3_STAGE;
        #pragma unroll
        for (int ks = 0; ks < 2; ks++) {
            uint32_t af[4];
            ldsm_x4(af, aBase + so + ks * 32);
            #pragma unroll
            for (int p = 0; p < 9; p++) {
                uint32_t bp[4];
                ldsm_x4(bp, bBase + so + p * (16 * 80) + ks * 32);
                uint32_t b0[2] = { bp[0], bp[1] };
                uint32_t b1[2] = { bp[2], bp[3] };
                mma_h(acc[p * 2],     af, b0);
                mma_h(acc[p * 2 + 1], af, b1);
            }
        }
        __syncthreads();
    }

    // ---- scale + bias ----
    const int m0 = rowBase + warp * 16 + g;
    #pragma unroll
    for (int nt = 0; nt < 18; nt++) {
        int n = nt * 8 + 2 * t;
        float2 bA = *(const float2*)&bias[m0 * S_ + n];
        float2 bB = *(const float2*)&bias[(m0 + 8) * S_ + n];
        acc[nt][0] = fmaf(acc[nt][0], scale, bA.x);
        acc[nt][1] = fmaf(acc[nt][1], scale, bA.y);
        acc[nt][2] = fmaf(acc[nt][2], scale, bB.x);
        acc[nt][3] = fmaf(acc[nt][3], scale, bB.y);
    }

    // ---- softmax fully in-warp ----
    float mx0 = -INFINITY, mx1 = -INFINITY;
    #pragma unroll
    for (int nt = 0; nt < 18; nt++) {
        mx0 = fmaxf(mx0, fmaxf(acc[nt][0], acc[nt][1]));
        mx1 = fmaxf(mx1, fmaxf(acc[nt][2], acc[nt][3]));
    }
    #pragma unroll
    for (int o = 1; o < 4; o <<= 1) {
        mx0 = fmaxf(mx0, __shfl_xor_sync(0xffffffffu, mx0, o));
        mx1 = fmaxf(mx1, __shfl_xor_sync(0xffffffffu, mx1, o));
    }
    float s0 = 0.f, s1 = 0.f;
    #pragma unroll
    for (int nt = 0; nt < 18; nt++) {
        acc[nt][0] = __expf(acc[nt][0] - mx0);
        acc[nt][1] = __expf(acc[nt][1] - mx0);
        acc[nt][2] = __expf(acc[nt][2] - mx1);
        acc[nt][3] = __expf(acc[nt][3] - mx1);
        s0 += acc[nt][0] + acc[nt][1];
        s1 += acc[nt][2] + acc[nt][3];
    }
    #pragma unroll
    for (int o = 1; o < 4; o <<= 1) {
        s0 += __shfl_xor_sync(0xffffffffu, s0, o);
        s1 += __shfl_xor_sync(0xffffffffu, s1, o);
    }
    const float i0 = 1.f / s0;
    const float i1 = 1.f / s1;

    // ---- repack attn into fp16 A-fragments ----
    uint32_t afr[9][4];
    #pragma unroll
    for (int s = 0; s < 9; s++) {
        afr[s][0] = pack_h2(acc[2 * s][0] * i0,     acc[2 * s][1] * i0);
        afr[s][1] = pack_h2(acc[2 * s][2] * i1,     acc[2 * s][3] * i1);
        afr[s][2] = pack_h2(acc[2 * s + 1][0] * i0, acc[2 * s + 1][1] * i0);
        afr[s][3] = pack_h2(acc[2 * s + 1][2] * i1, acc[2 * s + 1][3] * i1);
    }

    // ---- PV phase: v chunk row-major [144 k][72 halves], ldsm.trans B ----
    // lane offset inside a 16k x 16n ldsm.x4.trans group:
    //   k' = (lane&7) + ((lane>>3)&1)*8, n' = (lane>>4)*8
    const uint32_t vLane = sb +
        (uint32_t)(((lane & 7) + ((lane >> 3) & 1) * 8) * VROW + (lane >> 4) * 16);

    float* ob = out + (size_t)b * S_ * D_;

    for (int nc = 0; nc < 16; nc++) {
        const int colBase = nc * 64;
        // fill: 144 rows x 8 uint4 = 1152 / 96 thr = 12 each (coalesced)
        #pragma unroll
        for (int j = 0; j < 12; j++) {
            int idx = tid + j * 96;
            int tk  = idx >> 3;            // 0..143
            int dch = idx & 7;             // 0..7
            uint4 u = *(const uint4*)&vb[(size_t)tk * D_ + colBase + dch * 8];
            *(uint4*)(smc + tk * VROW + dch * 16) = u;
        }
        __syncthreads();

        float accPV[8][4];
        #pragma unroll
        for (int j = 0; j < 8; j++)
            #pragma unroll
            for (int r = 0; r < 4; r++) accPV[j][r] = 0.f;

        #pragma unroll
        for (int s = 0; s < 9; s++) {
            #pragma unroll
            for (int ng = 0; ng < 4; ng++) {
                uint32_t bp[4];
                ldsm_x4_t(bp, vLane + s * (16 * VROW) + ng * 32);
                uint32_t b0[2] = { bp[0], bp[1] };
                uint32_t b1[2] = { bp[2], bp[3] };
                mma_h(accPV[ng * 2],     afr[s], b0);
                mma_h(accPV[ng * 2 + 1], afr[s], b1);
            }
        }

        #pragma unroll
        for (int j = 0; j < 8; j++) {
            int n = colBase + j * 8 + 2 * t;
            float2 o0 = { accPV[j][0], accPV[j][1] };
            float2 o1 = { accPV[j][2], accPV[j][3] };
            *(float2*)&ob[(size_t)m0 * D_ + n]       = o0;
            *(float2*)&ob[(size_t)(m0 + 8) * D_ + n] = o1;
        }
        __syncthreads();
    }
}

// ============================================================================
// launch — 4 kernels, single stream
// ============================================================================
extern "C" void kernel_launch(void* const* d_in, const int* in_sizes, int n_in,
                              void* d_out, int out_size)
{
    const float* query = (const float*)d_in[0];
    const float* key   = (const float*)d_in[1];
    const float* value = (const float*)d_in[2];
    const float* Wq    = (const float*)d_in[3];
    const float* bq    = (const float*)d_in[4];
    const float* Wk    = (const float*)d_in[5];
    const float* bk    = (const float*)d_in[6];
    const float* Wv    = (const float*)d_in[7];
    const float* bv    = (const float*)d_in[8];
    const float* Wl    = (const float*)d_in[9];
    const float* bl    = (const float*)d_in[10];
    const float* wg    = (const float*)d_in[11];
    float* out = (float*)d_out;

    __half* ah;   cudaGetSymbolAddress((void**)&ah,   g_ah);
    __half* qh;   cudaGetSymbolAddress((void**)&qh,   g_q);
    __half* kh;   cudaGetSymbolAddress((void**)&kh,   g_k);
    __half* vh;   cudaGetSymbolAddress((void**)&vh,   g_v);
    __half* wt;   cudaGetSymbolAddress((void**)&wt,   g_wt);
    float* bias;  cudaGetSymbolAddress((void**)&bias, g_bias);

    cudaFuncSetAttribute(proj_h2,
                         cudaFuncAttributeMaxDynamicSharedMemorySize, PROJ_SMEM);
    cudaFuncSetAttribute(scores_av,
                         cudaFuncAttributeMaxDynamicSharedMemorySize, SAV_SMEM);

    float scale = 1.0f / sqrtf((float)D_);

    // 1. setup: input cvt + weight transpose (lean)
    setup_fused<<<SETUP_BLOCKS, 256>>>(query, key, value, ah, Wq, Wk, Wv, wt);

    // 2. bias table (rel inline, register-heavy, isolated)
    bias_kernel<<<dim3(144, 4), 256>>>(Wl, bl, wg, bias);

    // 3. projections (fp16 HMMA)
    proj_h2<<<dim3(8, 144, 3), 256, PROJ_SMEM>>>(ah, wt, bq, bk, bv, qh, kh, vh);

    // 4. fused attention: scores + softmax + @v
    scores_av<<<dim3(3, B_), 96, SAV_SMEM>>>(qh, kh, vh, bias, out, scale);
}